// round 2
// baseline (speedup 1.0000x reference)
#include <cuda_runtime.h>
#include <math_constants.h>

#define BATCH 16
#define H 1024
#define W 1024
#define HW (H * W)
#define TOPKN 512
#define CAP 131072

static __device__ float g_resp[(size_t)BATCH * HW];
static __device__ unsigned int g_imgmax[BATCH];
static __device__ int g_candcount[BATCH];
static __device__ unsigned long long g_cands[BATCH][CAP];

__device__ __forceinline__ unsigned int ford(float f) {
    unsigned int u = __float_as_uint(f);
    return (u & 0x80000000u) ? ~u : (u | 0x80000000u);
}
__device__ __forceinline__ float finv(unsigned int u) {
    u = (u & 0x80000000u) ? (u & 0x7fffffffu) : ~u;
    return __uint_as_float(u);
}

__global__ void reset_kernel() {
    int t = threadIdx.x;
    if (t < BATCH) { g_imgmax[t] = 0u; g_candcount[t] = 0; }
}

// ---------------------------------------------------------------------------
// K1: row-pipelined resp. Strip 512 cols x 64 rows, 256 threads (2 cols each).
// Sobel + 7x7 box exactly in int32; vertical box via register-ring sliding sum.
// ---------------------------------------------------------------------------
#define SW_ 512
#define SH_ 64
#define QW 528   // 520 used (512 + 2*4 halo)

__global__ __launch_bounds__(256) void resp_kernel(const float* __restrict__ im) {
    const int b = blockIdx.z;
    const int X0 = blockIdx.x * SW_;
    const int y0 = blockIdx.y * SH_;
    const int t = threadIdx.x;
    __shared__ int sq[4][QW];
    __shared__ int sP[2][3][QW];
    __shared__ unsigned int swmax[8];

    const float* imb = im + (size_t)b * HW;
    float* rb = g_resp + (size_t)b * HW;

    auto loadQ = [&](int rr) {
        int* dst = sq[rr & 3];
        if ((unsigned)rr < H) {
            const float* rowp = imb + (size_t)rr * W;
            float2 v = *(const float2*)(rowp + X0 + 2 * t);
            int2 q2;
            q2.x = __float2int_rd(v.x * 255.0f);
            q2.y = __float2int_rd(v.y * 255.0f);
            *(int2*)(dst + 4 + 2 * t) = q2;
            if (t < 8) {
                int ch = (t < 4) ? t : (512 + t);
                int gh = X0 - 4 + ch;
                dst[ch] = ((unsigned)gh < W) ? __float2int_rd(rowp[gh] * 255.0f) : 0;
            }
        } else {
            *(int2*)(dst + 4 + 2 * t) = make_int2(0, 0);
            if (t < 8) { int ch = (t < 4) ? t : (512 + t); dst[ch] = 0; }
        }
    };

    loadQ(y0 - 4); loadQ(y0 - 3); loadQ(y0 - 2);
    __syncthreads();

    int rgA[7][2], rgB[7][2], rgC[7][2];
#pragma unroll
    for (int k = 0; k < 7; k++) {
        rgA[k][0] = rgA[k][1] = 0; rgB[k][0] = rgB[k][1] = 0; rgC[k][0] = rgC[k][1] = 0;
    }
    int smA0 = 0, smA1 = 0, smB0 = 0, smB1 = 0, smC0 = 0, smC1 = 0;
    unsigned int mloc = 0;
    const int c0 = 2 * t;

    for (int ii = 0; ii < 70; ii += 7) {
#pragma unroll
        for (int k = 0; k < 7; k++) {
            const int i = ii + k;           // 0..69, i % 7 == k (static ring slot)
            const int pr = y0 - 3 + i;      // product row
            const int buf = i & 1;

            loadQ(pr + 2);

            {   // products row pr (Sobel grads from zero-padded q; zero outside image)
                const int* qm = sq[(pr - 1) & 3];
                const int* qc = sq[pr & 3];
                const int* qp = sq[(pr + 1) & 3];
                const bool rowin = ((unsigned)pr < H);
                int* pA = sP[buf][0]; int* pB = sP[buf][1]; int* pC = sP[buf][2];
                for (int j = t; j < 259; j += 256) {
                    const int p = 2 * j;
                    int A0 = 0, A1 = 0, B0 = 0, B1 = 0, C0 = 0, C1 = 0;
                    if (rowin) {
                        int2 m01 = *(const int2*)(qm + p); int2 m23 = *(const int2*)(qm + p + 2);
                        int2 c01 = *(const int2*)(qc + p); int2 c23 = *(const int2*)(qc + p + 2);
                        int2 p01 = *(const int2*)(qp + p); int2 p23 = *(const int2*)(qp + p + 2);
                        int g0 = X0 - 3 + p;
                        if ((unsigned)g0 < W) {
                            int gx = (m23.x - m01.x) + 2 * (c23.x - c01.x) + (p23.x - p01.x);
                            int gy = (p01.x + 2 * p01.y + p23.x) - (m01.x + 2 * m01.y + m23.x);
                            A0 = gx * gx; B0 = gx * gy; C0 = gy * gy;
                        }
                        if ((unsigned)(g0 + 1) < W) {
                            int gx = (m23.y - m01.y) + 2 * (c23.y - c01.y) + (p23.y - p01.y);
                            int gy = (p01.y + 2 * p23.x + p23.y) - (m01.y + 2 * m23.x + m23.y);
                            A1 = gx * gx; B1 = gx * gy; C1 = gy * gy;
                        }
                    }
                    *(int2*)(pA + p) = make_int2(A0, A1);
                    *(int2*)(pB + p) = make_int2(B0, B1);
                    *(int2*)(pC + p) = make_int2(C0, C1);
                }
            }
            __syncthreads();

            {   // horizontal 7-sums for cols c0, c0+1 (products c0..c0+7)
                const int* pA = sP[buf][0]; const int* pB = sP[buf][1]; const int* pC = sP[buf][2];
                int2 a01 = *(const int2*)(pA + c0), a23 = *(const int2*)(pA + c0 + 2);
                int2 a45 = *(const int2*)(pA + c0 + 4), a67 = *(const int2*)(pA + c0 + 6);
                int sa = a01.y + a23.x + a23.y + a45.x + a45.y + a67.x;
                int hA0 = a01.x + sa, hA1 = sa + a67.y;
                int2 b01 = *(const int2*)(pB + c0), b23 = *(const int2*)(pB + c0 + 2);
                int2 b45 = *(const int2*)(pB + c0 + 4), b67 = *(const int2*)(pB + c0 + 6);
                int sb = b01.y + b23.x + b23.y + b45.x + b45.y + b67.x;
                int hB0 = b01.x + sb, hB1 = sb + b67.y;
                int2 e01 = *(const int2*)(pC + c0), e23 = *(const int2*)(pC + c0 + 2);
                int2 e45 = *(const int2*)(pC + c0 + 4), e67 = *(const int2*)(pC + c0 + 6);
                int se = e01.y + e23.x + e23.y + e45.x + e45.y + e67.x;
                int hC0 = e01.x + se, hC1 = se + e67.y;

                // vertical sliding window (ring slot k is compile-time)
                smA0 += hA0 - rgA[k][0]; rgA[k][0] = hA0;
                smA1 += hA1 - rgA[k][1]; rgA[k][1] = hA1;
                smB0 += hB0 - rgB[k][0]; rgB[k][0] = hB0;
                smB1 += hB1 - rgB[k][1]; rgB[k][1] = hB1;
                smC0 += hC0 - rgC[k][0]; rgC[k][0] = hC0;
                smC1 += hC1 - rgC[k][1]; rgC[k][1] = hC1;

                if (i >= 6) {
                    const int orow = pr - 3;
                    float fa = (float)smA0, fc = (float)smC0, fb = (float)smB0;
                    float dd = __fsub_rn(fa, fc);
                    float s  = __fadd_rn(__fmul_rn(dd, dd), __fmul_rn(__fmul_rn(4.0f, fb), fb));
                    float r0 = 0.5f * __fsub_rn(__fadd_rn(fa, fc), __fsqrt_rn(s));
                    float fa1 = (float)smA1, fc1 = (float)smC1, fb1 = (float)smB1;
                    float dd1 = __fsub_rn(fa1, fc1);
                    float s1  = __fadd_rn(__fmul_rn(dd1, dd1), __fmul_rn(__fmul_rn(4.0f, fb1), fb1));
                    float r1 = 0.5f * __fsub_rn(__fadd_rn(fa1, fc1), __fsqrt_rn(s1));
                    *(float2*)(rb + (size_t)orow * W + X0 + c0) = make_float2(r0, r1);
                    unsigned int k0 = ford(r0), k1 = ford(r1);
                    if (k0 > mloc) mloc = k0;
                    if (k1 > mloc) mloc = k1;
                }
            }
        }
    }

#pragma unroll
    for (int o = 16; o; o >>= 1) {
        unsigned int v = __shfl_xor_sync(0xffffffffu, mloc, o);
        if (v > mloc) mloc = v;
    }
    if ((t & 31) == 0) swmax[t >> 5] = mloc;
    __syncthreads();
    if (t == 0) {
        unsigned int m = swmax[0];
#pragma unroll
        for (int w = 1; w < 8; ++w) if (swmax[w] > m) m = swmax[w];
        atomicMax(&g_imgmax[b], m);
    }
}

// ---------------------------------------------------------------------------
// K2: NMS via 3x3-max pyramid. 15x15 max == max of 5x5 stride-3 grid of 3x3
// maxes (offsets {-6,-3,0,3,6} +/-1 cover [-7..7]). Prune, then verify
// survivors via a compacted shared list.
// ---------------------------------------------------------------------------
#define SURVCAP 768

__global__ __launch_bounds__(256) void nms_kernel() {
    const int b = blockIdx.z;
    const int X0 = blockIdx.x * 32, Y0 = blockIdx.y * 32;
    __shared__ float sr[46][48];
    __shared__ float h3[46][48];
    __shared__ float m3[44][48];
    __shared__ float sv[SURVCAP];
    __shared__ int srthings[SURVCAP];
    __shared__ int scount;
    const int t = threadIdx.x;
    const float* rbase = g_resp + (size_t)b * HW;

    if (t == 0) scount = 0;
    for (int i = t; i < 46 * 46; i += 256) {
        int r = i / 46, c = i % 46;
        int gy = Y0 - 7 + r, gxx = X0 - 7 + c;
        sr[r][c] = ((unsigned)gy < H && (unsigned)gxx < W) ? rbase[gy * W + gxx] : -CUDART_INF_F;
    }
    __syncthreads();

    // h3[r][x] = max(sr[r][x..x+2]), x in 0..43
    for (int i = t; i < 46 * 22; i += 256) {
        int r = i / 22, x = 2 * (i % 22);
        float2 f0 = *(float2*)&sr[r][x];
        float2 f1 = *(float2*)&sr[r][x + 2];
        float h0 = fmaxf(f0.x, fmaxf(f0.y, f1.x));
        float h1 = fmaxf(f0.y, fmaxf(f1.x, f1.y));
        *(float2*)&h3[r][x] = make_float2(h0, h1);
    }
    __syncthreads();

    // m3[r][x] = max(h3[r..r+2][x]) -> 3x3 max centered at sr(r+1, x+1)
    for (int i = t; i < 44 * 22; i += 256) {
        int r = i / 22, x = 2 * (i % 22);
        float2 a = *(float2*)&h3[r][x];
        float2 bb = *(float2*)&h3[r + 1][x];
        float2 cc = *(float2*)&h3[r + 2][x];
        float m0 = fmaxf(a.x, fmaxf(bb.x, cc.x));
        float m1 = fmaxf(a.y, fmaxf(bb.y, cc.y));
        *(float2*)&m3[r][x] = make_float2(m0, m1);
    }
    __syncthreads();

    const float thresh = 0.3f * finv(g_imgmax[b]);
    for (int i = t; i < 1024; i += 256) {
        int r = i >> 5, c = i & 31;
        float v = sr[r + 7][c + 7];
        if (v >= thresh && v >= m3[r + 6][c + 6]) {
            int s = atomicAdd(&scount, 1);
            if (s < SURVCAP) { sv[s] = v; srthings[s] = (r << 5) | c; }
        }
    }
    __syncthreads();

    int sc = scount < SURVCAP ? scount : SURVCAP;
    for (int i = t; i < sc; i += 256) {
        float v = sv[i];
        int rc = srthings[i];
        int r = rc >> 5, c = rc & 31;
        float m = -CUDART_INF_F;
#pragma unroll
        for (int di = 0; di < 5; di++)
#pragma unroll
            for (int dj = 0; dj < 5; dj++)
                m = fmaxf(m, m3[r + 3 * di][c + 3 * dj]);
        if (v >= m) {
            unsigned int idx = (unsigned)((Y0 + r) * W + (X0 + c));
            unsigned long long key =
                ((unsigned long long)ford(v) << 32) | (unsigned int)(~idx);
            int slot = atomicAdd(&g_candcount[b], 1);
            if (slot < CAP) g_cands[b][slot] = key;
        }
    }
}

// ---------------------------------------------------------------------------
// K3: exact top-512 via 6-pass 11-bit histogram radix select (keys unique),
// then bitonic sort 512, scatter mask + coords.
// ---------------------------------------------------------------------------
__global__ __launch_bounds__(512) void topk_kernel(float* __restrict__ out, int write_coords) {
    const int b = blockIdx.x;
    const int t = threadIdx.x;
    __shared__ int hist[2048];
    __shared__ int s_sth[512];
    __shared__ int s_ws[16];
    __shared__ unsigned long long skeys[TOPKN];
    __shared__ unsigned long long s_prefix;
    __shared__ int s_need;
    __shared__ int s_cnt;

    int n = g_candcount[b]; if (n > CAP) n = CAP;
    int Kb = n < TOPKN ? n : TOPKN;
    const unsigned long long* cb = g_cands[b];

    unsigned long long T = 0ull;
    if (Kb > 0) {
        if (t == 0) { s_prefix = 0ull; s_need = Kb; }
        __syncthreads();
        const int sh_arr[6] = {53, 42, 31, 20, 9, 0};
#pragma unroll 1
        for (int pass = 0; pass < 6; pass++) {
            const int sh = sh_arr[pass];
            const int width = (pass < 5) ? 11 : 9;
            const unsigned int mask = (1u << width) - 1u;
            for (int i = t; i < 2048; i += 512) hist[i] = 0;
            __syncthreads();
            unsigned long long pref = s_prefix;
            const int hb = sh + width;
            const bool all = (pass == 0);
            const unsigned long long ph = all ? 0ull : (pref >> hb);
            for (int i = t; i < n; i += 512) {
                unsigned long long k = cb[i];
                if (all || (k >> hb) == ph)
                    atomicAdd(&hist[(int)((k >> sh) & mask)], 1);
            }
            __syncthreads();
            int sth = hist[4 * t] + hist[4 * t + 1] + hist[4 * t + 2] + hist[4 * t + 3];
            s_sth[t] = sth;
            int wsum = sth;
#pragma unroll
            for (int o = 16; o; o >>= 1) wsum += __shfl_xor_sync(0xffffffffu, wsum, o);
            if ((t & 31) == 0) s_ws[t >> 5] = wsum;
            __syncthreads();
            if (t == 0) {
                int need = s_need, cum = 0, w, th, bin;
                for (w = 15; w > 0; w--) { int v = s_ws[w]; if (cum + v >= need) break; cum += v; }
                for (th = 31; th > 0; th--) { int v = s_sth[w * 32 + th]; if (cum + v >= need) break; cum += v; }
                int base = (w * 32 + th) * 4;
                for (bin = 3; bin > 0; bin--) { int v = hist[base + bin]; if (cum + v >= need) break; cum += v; }
                s_need = need - cum;
                s_prefix = pref | ((unsigned long long)(base + bin) << sh);
            }
            __syncthreads();
        }
        T = s_prefix;
    }

    if (t == 0) s_cnt = 0;
    __syncthreads();
    if (Kb > 0) {
        for (int i = t; i < n; i += 512) {
            unsigned long long k = cb[i];
            if (k >= T) {
                int p = atomicAdd(&s_cnt, 1);
                if (p < TOPKN) skeys[p] = k;
            }
        }
    }
    __syncthreads();
    int m = s_cnt < TOPKN ? s_cnt : TOPKN;
    if (t >= m) skeys[t] = 0ull;
    __syncthreads();

    for (int k = 2; k <= TOPKN; k <<= 1) {
        for (int j = k >> 1; j > 0; j >>= 1) {
            int ixj = t ^ j;
            if (ixj > t) {
                unsigned long long a = skeys[t], c = skeys[ixj];
                bool sw = ((t & k) == 0) ? (a < c) : (a > c);
                if (sw) { skeys[t] = c; skeys[ixj] = a; }
            }
            __syncthreads();
        }
    }

    unsigned long long key = skeys[t];
    if (key != 0ull) {
        unsigned int idx = ~((unsigned int)key);
        out[(size_t)b * HW + idx] = 1.0f;
        if (write_coords) {
            float* coords = out + (size_t)BATCH * HW;
            coords[((size_t)b * TOPKN + t) * 2 + 0] = (float)(idx >> 10);
            coords[((size_t)b * TOPKN + t) * 2 + 1] = (float)(idx & 1023u);
        }
    } else if (write_coords) {
        float* coords = out + (size_t)BATCH * HW;
        coords[((size_t)b * TOPKN + t) * 2 + 0] = -1.0f;
        coords[((size_t)b * TOPKN + t) * 2 + 1] = -1.0f;
    }
}

extern "C" void kernel_launch(void* const* d_in, const int* in_sizes, int n_in,
                              void* d_out, int out_size) {
    const float* im = (const float*)d_in[0];
    float* out = (float*)d_out;

    cudaMemsetAsync(d_out, 0, (size_t)out_size * sizeof(float));
    reset_kernel<<<1, 32>>>();

    dim3 grid1(W / SW_, H / SH_, BATCH);
    resp_kernel<<<grid1, 256>>>(im);

    dim3 grid2(W / 32, H / 32, BATCH);
    nms_kernel<<<grid2, 256>>>();

    int wc = (out_size >= BATCH * HW + BATCH * TOPKN * 2) ? 1 : 0;
    topk_kernel<<<BATCH, 512>>>(out, wc);
}

// round 5
// speedup vs baseline: 1.1644x; 1.1644x over previous
#include <cuda_runtime.h>
#include <math_constants.h>

#define BATCH 16
#define H 1024
#define W 1024
#define HW (H * W)
#define TOPKN 512
#define CAP 131072

static __device__ float g_resp[(size_t)BATCH * HW];
static __device__ unsigned int g_imgmax[BATCH];
static __device__ int g_candcount[BATCH];
static __device__ unsigned long long g_cands[BATCH][CAP];

__device__ __forceinline__ unsigned int ford(float f) {
    unsigned int u = __float_as_uint(f);
    return (u & 0x80000000u) ? ~u : (u | 0x80000000u);
}
__device__ __forceinline__ float finv(unsigned int u) {
    u = (u & 0x80000000u) ? (u & 0x7fffffffu) : ~u;
    return __uint_as_float(u);
}

__global__ void reset_kernel() {
    int t = threadIdx.x;
    if (t < BATCH) { g_imgmax[t] = 0u; g_candcount[t] = 0; }
}

// ---------------------------------------------------------------------------
// K1: warp-shuffle Shi-Tomasi response. No smem, no barriers.
// Each warp: 24 output cols (lanes 4..27) x 128 rows. Exact int arithmetic.
// Products zeroed outside image domain (rows AND cols). Vertical 7-row box
// via a 7-deep register ring (subtract h_{i-7}).
// ---------------------------------------------------------------------------
#define KCOLS 24
#define KROWS 128
#define WCOLS 43                    // ceil(1024/24)
#define WROWS (H / KROWS)           // 8
#define WARPS_PER_IMG (WCOLS * WROWS)   // 344
#define TOTAL_WARPS (BATCH * WARPS_PER_IMG)  // 5504
#define K1_BLOCKS (TOTAL_WARPS / 8) // 688

__global__ __launch_bounds__(256) void resp_kernel(const float* __restrict__ im) {
    const int wg = blockIdx.x * 8 + (threadIdx.x >> 5);
    const int lane = threadIdx.x & 31;
    const int b = wg / WARPS_PER_IMG;
    const int r = wg % WARPS_PER_IMG;
    const int wr = r / WCOLS;
    const int wc = r % WCOLS;
    const int col = wc * KCOLS - 4 + lane;
    const int y0 = wr * KROWS;
    const bool colin = ((unsigned)col < W);
    const bool outlane = (lane >= 4) && (lane < 28) && colin;
    const float* imb = im + (size_t)b * HW;
    float* rb = g_resp + (size_t)b * HW;

    auto loadrow = [&](int rr) -> int {
        return ((unsigned)rr < H && colin)
                   ? __float2int_rd(imb[(size_t)rr * W + col] * 255.0f)
                   : 0;
    };

    // q ring: qm=row pr-1, qc=pr, qp=pr+1, qn=pr+2 (prefetch)
    int qm = loadrow(y0 - 4);
    int qc = loadrow(y0 - 3);
    int qp = loadrow(y0 - 2);
    int qn = loadrow(y0 - 1);

    int rA[7], rB[7], rC[7];
#pragma unroll
    for (int j = 0; j < 7; j++) { rA[j] = 0; rB[j] = 0; rC[j] = 0; }
    int sA = 0, sB = 0, sC = 0;
    unsigned int mloc = 0;

    for (int i = 0; i < KROWS + 6; i++) {
        const int pr = y0 - 3 + i;          // product row
        const int qn2 = loadrow(pr + 3);    // prefetch 2 ahead

        // Sobel (correlation): gx = v[c+1]-v[c-1], v = qm+2qc+qp
        //                      gy = d[c-1]+2d[c]+d[c+1], d = qp-qm
        int A = 0, Bv = 0, C = 0;
        {
            int v = qm + 2 * qc + qp;
            int d = qp - qm;
            int gx = __shfl_down_sync(0xffffffffu, v, 1) -
                     __shfl_up_sync(0xffffffffu, v, 1);
            int gy = __shfl_up_sync(0xffffffffu, d, 1) + 2 * d +
                     __shfl_down_sync(0xffffffffu, d, 1);
            // products exist only on the image domain (zero-padded box filter)
            if (((unsigned)pr < H) & colin) {
                A = gx * gx; Bv = gx * gy; C = gy * gy;
            }
        }

        // Horizontal 7-sum: h[c] = x[c-3..c+3]
        //   s1[c]=x[c]+x[c+1]; s2[c]=s1[c]+s1[c+2]=x[c..c+3]
        //   h[c] = s2[c-3] + s2[c+1] - x[c+4]   (exact int cancellation)
        int hA, hB, hC;
        {
            int s1 = A + __shfl_down_sync(0xffffffffu, A, 1);
            int s2 = s1 + __shfl_down_sync(0xffffffffu, s1, 2);
            hA = __shfl_up_sync(0xffffffffu, s2, 3) +
                 __shfl_down_sync(0xffffffffu, s2, 1) -
                 __shfl_down_sync(0xffffffffu, A, 4);
        }
        {
            int s1 = Bv + __shfl_down_sync(0xffffffffu, Bv, 1);
            int s2 = s1 + __shfl_down_sync(0xffffffffu, s1, 2);
            hB = __shfl_up_sync(0xffffffffu, s2, 3) +
                 __shfl_down_sync(0xffffffffu, s2, 1) -
                 __shfl_down_sync(0xffffffffu, Bv, 4);
        }
        {
            int s1 = C + __shfl_down_sync(0xffffffffu, C, 1);
            int s2 = s1 + __shfl_down_sync(0xffffffffu, s1, 2);
            hC = __shfl_up_sync(0xffffffffu, s2, 3) +
                 __shfl_down_sync(0xffffffffu, s2, 1) -
                 __shfl_down_sync(0xffffffffu, C, 4);
        }

        // Vertical sliding 7-sum: subtract h_{i-7} (ring depth 7!)
        sA += hA - rA[0];
        sB += hB - rB[0];
        sC += hC - rC[0];
#pragma unroll
        for (int j = 0; j < 6; j++) { rA[j] = rA[j + 1]; rB[j] = rB[j + 1]; rC[j] = rC[j + 1]; }
        rA[6] = hA; rB[6] = hB; rC[6] = hC;

        if (i >= 6) {
            float fa = (float)sA, fc = (float)sC, fb = (float)sB;
            float dd = __fsub_rn(fa, fc);
            float s  = __fadd_rn(__fmul_rn(dd, dd), __fmul_rn(__fmul_rn(4.0f, fb), fb));
            float resp = 0.5f * __fsub_rn(__fadd_rn(fa, fc), __fsqrt_rn(s));
            if (outlane) {
                rb[(size_t)(pr - 3) * W + col] = resp;
                unsigned int k = ford(resp);
                if (k > mloc) mloc = k;
            }
        }

        qm = qc; qc = qp; qp = qn; qn = qn2;
    }

#pragma unroll
    for (int o = 16; o; o >>= 1) {
        unsigned int v = __shfl_xor_sync(0xffffffffu, mloc, o);
        if (v > mloc) mloc = v;
    }
    if (lane == 0) atomicMax(&g_imgmax[b], mloc);
}

// ---------------------------------------------------------------------------
// K2: NMS via 3x3-max pyramid (15x15 max = 5x5 stride-3 grid of 3x3 maxes).
// ---------------------------------------------------------------------------
#define SURVCAP 768

__global__ __launch_bounds__(256) void nms_kernel() {
    const int b = blockIdx.z;
    const int X0 = blockIdx.x * 32, Y0 = blockIdx.y * 32;
    __shared__ float sr[46][48];
    __shared__ float h3[46][48];
    __shared__ float m3[44][48];
    __shared__ float sv[SURVCAP];
    __shared__ int srthings[SURVCAP];
    __shared__ int scount;
    const int t = threadIdx.x;
    const float* rbase = g_resp + (size_t)b * HW;

    if (t == 0) scount = 0;
    for (int i = t; i < 46 * 46; i += 256) {
        int r = i / 46, c = i % 46;
        int gy = Y0 - 7 + r, gxx = X0 - 7 + c;
        sr[r][c] = ((unsigned)gy < H && (unsigned)gxx < W) ? rbase[gy * W + gxx] : -CUDART_INF_F;
    }
    __syncthreads();

    for (int i = t; i < 46 * 22; i += 256) {
        int r = i / 22, x = 2 * (i % 22);
        float2 f0 = *(float2*)&sr[r][x];
        float2 f1 = *(float2*)&sr[r][x + 2];
        float h0 = fmaxf(f0.x, fmaxf(f0.y, f1.x));
        float h1 = fmaxf(f0.y, fmaxf(f1.x, f1.y));
        *(float2*)&h3[r][x] = make_float2(h0, h1);
    }
    __syncthreads();

    for (int i = t; i < 44 * 22; i += 256) {
        int r = i / 22, x = 2 * (i % 22);
        float2 a = *(float2*)&h3[r][x];
        float2 bb = *(float2*)&h3[r + 1][x];
        float2 cc = *(float2*)&h3[r + 2][x];
        float m0 = fmaxf(a.x, fmaxf(bb.x, cc.x));
        float m1 = fmaxf(a.y, fmaxf(bb.y, cc.y));
        *(float2*)&m3[r][x] = make_float2(m0, m1);
    }
    __syncthreads();

    const float thresh = 0.3f * finv(g_imgmax[b]);
    for (int i = t; i < 1024; i += 256) {
        int r = i >> 5, c = i & 31;
        float v = sr[r + 7][c + 7];
        if (v >= thresh && v >= m3[r + 6][c + 6]) {
            int s = atomicAdd(&scount, 1);
            if (s < SURVCAP) { sv[s] = v; srthings[s] = (r << 5) | c; }
        }
    }
    __syncthreads();

    int sc = scount < SURVCAP ? scount : SURVCAP;
    for (int i = t; i < sc; i += 256) {
        float v = sv[i];
        int rc = srthings[i];
        int r = rc >> 5, c = rc & 31;
        float m = -CUDART_INF_F;
#pragma unroll
        for (int di = 0; di < 5; di++)
#pragma unroll
            for (int dj = 0; dj < 5; dj++)
                m = fmaxf(m, m3[r + 3 * di][c + 3 * dj]);
        if (v >= m) {
            unsigned int idx = (unsigned)((Y0 + r) * W + (X0 + c));
            unsigned long long key =
                ((unsigned long long)ford(v) << 32) | (unsigned int)(~idx);
            int slot = atomicAdd(&g_candcount[b], 1);
            if (slot < CAP) g_cands[b][slot] = key;
        }
    }
}

// ---------------------------------------------------------------------------
// K3: exact top-512 via 6-pass 11-bit histogram radix select, bitonic sort,
// scatter mask + coords.
// ---------------------------------------------------------------------------
__global__ __launch_bounds__(512) void topk_kernel(float* __restrict__ out, int write_coords) {
    const int b = blockIdx.x;
    const int t = threadIdx.x;
    __shared__ int hist[2048];
    __shared__ int s_sth[512];
    __shared__ int s_ws[16];
    __shared__ unsigned long long skeys[TOPKN];
    __shared__ unsigned long long s_prefix;
    __shared__ int s_need;
    __shared__ int s_cnt;

    int n = g_candcount[b]; if (n > CAP) n = CAP;
    int Kb = n < TOPKN ? n : TOPKN;
    const unsigned long long* cb = g_cands[b];

    unsigned long long T = 0ull;
    if (Kb > 0) {
        if (t == 0) { s_prefix = 0ull; s_need = Kb; }
        __syncthreads();
        const int sh_arr[6] = {53, 42, 31, 20, 9, 0};
#pragma unroll 1
        for (int pass = 0; pass < 6; pass++) {
            const int sh = sh_arr[pass];
            const int width = (pass < 5) ? 11 : 9;
            const unsigned int mask = (1u << width) - 1u;
            for (int i = t; i < 2048; i += 512) hist[i] = 0;
            __syncthreads();
            unsigned long long pref = s_prefix;
            const int hb = sh + width;
            const bool all = (pass == 0);
            const unsigned long long ph = all ? 0ull : (pref >> hb);
            for (int i = t; i < n; i += 512) {
                unsigned long long k = cb[i];
                if (all || (k >> hb) == ph)
                    atomicAdd(&hist[(int)((k >> sh) & mask)], 1);
            }
            __syncthreads();
            int sth = hist[4 * t] + hist[4 * t + 1] + hist[4 * t + 2] + hist[4 * t + 3];
            s_sth[t] = sth;
            int wsum = sth;
#pragma unroll
            for (int o = 16; o; o >>= 1) wsum += __shfl_xor_sync(0xffffffffu, wsum, o);
            if ((t & 31) == 0) s_ws[t >> 5] = wsum;
            __syncthreads();
            if (t == 0) {
                int need = s_need, cum = 0, w, th, bin;
                for (w = 15; w > 0; w--) { int v = s_ws[w]; if (cum + v >= need) break; cum += v; }
                for (th = 31; th > 0; th--) { int v = s_sth[w * 32 + th]; if (cum + v >= need) break; cum += v; }
                int base = (w * 32 + th) * 4;
                for (bin = 3; bin > 0; bin--) { int v = hist[base + bin]; if (cum + v >= need) break; cum += v; }
                s_need = need - cum;
                s_prefix = pref | ((unsigned long long)(base + bin) << sh);
            }
            __syncthreads();
        }
        T = s_prefix;
    }

    if (t == 0) s_cnt = 0;
    __syncthreads();
    if (Kb > 0) {
        for (int i = t; i < n; i += 512) {
            unsigned long long k = cb[i];
            if (k >= T) {
                int p = atomicAdd(&s_cnt, 1);
                if (p < TOPKN) skeys[p] = k;
            }
        }
    }
    __syncthreads();
    int m = s_cnt < TOPKN ? s_cnt : TOPKN;
    if (t >= m) skeys[t] = 0ull;
    __syncthreads();

    for (int k = 2; k <= TOPKN; k <<= 1) {
        for (int j = k >> 1; j > 0; j >>= 1) {
            int ixj = t ^ j;
            if (ixj > t) {
                unsigned long long a = skeys[t], c = skeys[ixj];
                bool sw = ((t & k) == 0) ? (a < c) : (a > c);
                if (sw) { skeys[t] = c; skeys[ixj] = a; }
            }
            __syncthreads();
        }
    }

    unsigned long long key = skeys[t];
    if (key != 0ull) {
        unsigned int idx = ~((unsigned int)key);
        out[(size_t)b * HW + idx] = 1.0f;
        if (write_coords) {
            float* coords = out + (size_t)BATCH * HW;
            coords[((size_t)b * TOPKN + t) * 2 + 0] = (float)(idx >> 10);
            coords[((size_t)b * TOPKN + t) * 2 + 1] = (float)(idx & 1023u);
        }
    } else if (write_coords) {
        float* coords = out + (size_t)BATCH * HW;
        coords[((size_t)b * TOPKN + t) * 2 + 0] = -1.0f;
        coords[((size_t)b * TOPKN + t) * 2 + 1] = -1.0f;
    }
}

extern "C" void kernel_launch(void* const* d_in, const int* in_sizes, int n_in,
                              void* d_out, int out_size) {
    const float* im = (const float*)d_in[0];
    float* out = (float*)d_out;

    cudaMemsetAsync(d_out, 0, (size_t)out_size * sizeof(float));
    reset_kernel<<<1, 32>>>();

    resp_kernel<<<K1_BLOCKS, 256>>>(im);

    dim3 grid2(W / 32, H / 32, BATCH);
    nms_kernel<<<grid2, 256>>>();

    int wc = (out_size >= BATCH * HW + BATCH * TOPKN * 2) ? 1 : 0;
    topk_kernel<<<BATCH, 512>>>(out, wc);
}